// round 4
// baseline (speedup 1.0000x reference)
#include <cuda_runtime.h>
#include <stdint.h>

// SkipGramNS: out[i] = dot(cxt_weight[ctx_idx[i]], tgt_weight[tgt_idx[i]])
// N=1e6, D=128, V=1e5.
//
// R3 profile: DRAM 53%, L2 60%, issue 21% -> still latency-bound.
// This version: 4 lanes per pair, 8 pairs per warp.
//   - each lane: 8 independent float4 loads per table (MLP=16, was 8)
//   - 4-lane group reads 64B contiguous per load instruction (full sectors)
//   - 2-step butterfly reduce within each 4-lane group
//   - indices via __ldcs / output via __stcs (streaming; don't pollute the
//     L2 that is holding the ~102MB of embedding tables)

__global__ void __launch_bounds__(256)
skipgram_dot_kernel(const int* __restrict__ ctx_idx,
                    const int* __restrict__ tgt_idx,
                    const float* __restrict__ cxt_w,
                    const float* __restrict__ tgt_w,
                    float* __restrict__ out,
                    int n)
{
    const int warp_id = (blockIdx.x * blockDim.x + threadIdx.x) >> 5;
    const int lane    = threadIdx.x & 31;
    const int group   = lane >> 2;   // 0..7: which pair within the warp
    const int j       = lane & 3;    // 0..3: lane within group

    const int pair = warp_id * 8 + group;
    if (pair >= n) return;

    const long long c = (long long)__ldcs(&ctx_idx[pair]);
    const long long t = (long long)__ldcs(&tgt_idx[pair]);

    const float4* __restrict__ cv =
        reinterpret_cast<const float4*>(cxt_w + c * 128);
    const float4* __restrict__ tv =
        reinterpret_cast<const float4*>(tgt_w + t * 128);

    // 16 independent 16B loads per lane -> MLP=16
    float4 a[8], b[8];
    #pragma unroll
    for (int k = 0; k < 8; k++)
        a[k] = __ldg(&cv[j + 4 * k]);
    #pragma unroll
    for (int k = 0; k < 8; k++)
        b[k] = __ldg(&tv[j + 4 * k]);

    float s0 = 0.f, s1 = 0.f, s2 = 0.f, s3 = 0.f;
    #pragma unroll
    for (int k = 0; k < 8; k += 4) {
        s0 = fmaf(a[k+0].x, b[k+0].x, s0);
        s0 = fmaf(a[k+0].y, b[k+0].y, s0);
        s0 = fmaf(a[k+0].z, b[k+0].z, s0);
        s0 = fmaf(a[k+0].w, b[k+0].w, s0);
        s1 = fmaf(a[k+1].x, b[k+1].x, s1);
        s1 = fmaf(a[k+1].y, b[k+1].y, s1);
        s1 = fmaf(a[k+1].z, b[k+1].z, s1);
        s1 = fmaf(a[k+1].w, b[k+1].w, s1);
        s2 = fmaf(a[k+2].x, b[k+2].x, s2);
        s2 = fmaf(a[k+2].y, b[k+2].y, s2);
        s2 = fmaf(a[k+2].z, b[k+2].z, s2);
        s2 = fmaf(a[k+2].w, b[k+2].w, s2);
        s3 = fmaf(a[k+3].x, b[k+3].x, s3);
        s3 = fmaf(a[k+3].y, b[k+3].y, s3);
        s3 = fmaf(a[k+3].z, b[k+3].z, s3);
        s3 = fmaf(a[k+3].w, b[k+3].w, s3);
    }
    float s = (s0 + s1) + (s2 + s3);

    // butterfly reduce across the 4-lane group (xor 2,1 stays in-group)
    s += __shfl_xor_sync(0xFFFFFFFFu, s, 2);
    s += __shfl_xor_sync(0xFFFFFFFFu, s, 1);

    if (j == 0)
        __stcs(&out[pair], s);
}

extern "C" void kernel_launch(void* const* d_in, const int* in_sizes, int n_in,
                              void* d_out, int out_size)
{
    const int*   ctx_idx = (const int*)d_in[0];
    const int*   tgt_idx = (const int*)d_in[1];
    const float* cxt_w   = (const float*)d_in[2];
    const float* tgt_w   = (const float*)d_in[3];
    float*       out     = (float*)d_out;

    const int n = in_sizes[0];               // 1,000,000 pairs
    const int threads = 256;                 // 8 warps/block, 64 pairs/block
    const int pairs_per_block = (threads / 32) * 8;
    const int blocks = (n + pairs_per_block - 1) / pairs_per_block;

    skipgram_dot_kernel<<<blocks, threads>>>(ctx_idx, tgt_idx, cxt_w, tgt_w, out, n);
}

// round 6
// speedup vs baseline: 1.5949x; 1.5949x over previous
#include <cuda_runtime.h>
#include <stdint.h>

// SkipGramNS: out[i] = dot(cxt_weight[ctx_idx[i]], tgt_weight[tgt_idx[i]])
// N=1e6, D=128, V=1e5.
//
// R6: 256-bit loads (LDG.256, sm_103a) with L2::evict_last (only legal on
// .v8.b32/.v4.b64 — per R5's ptxas error). Geometry: 4-lane groups, each
// group owns one pair, 8 pairs/warp. Each instruction: 4 lanes x 32B = one
// full 128B line per row (same L1 wavefronts/row as the 69.8us R3 kernel),
// but 2x in-flight bytes per warp and half the LDG instructions.

__device__ __forceinline__ void ldg256_keep(const float* p, float v[8]) {
    asm("ld.global.nc.L2::evict_last.v8.b32 {%0,%1,%2,%3,%4,%5,%6,%7}, [%8];"
        : "=f"(v[0]), "=f"(v[1]), "=f"(v[2]), "=f"(v[3]),
          "=f"(v[4]), "=f"(v[5]), "=f"(v[6]), "=f"(v[7])
        : "l"(p));
}

__global__ void __launch_bounds__(128)
skipgram_dot_kernel(const int* __restrict__ ctx_idx,
                    const int* __restrict__ tgt_idx,
                    const float* __restrict__ cxt_w,
                    const float* __restrict__ tgt_w,
                    float* __restrict__ out,
                    int n)
{
    const int warp_id = (blockIdx.x * blockDim.x + threadIdx.x) >> 5;
    const int lane    = threadIdx.x & 31;
    const int group   = lane >> 2;   // 0..7: pair within warp
    const int j       = lane & 3;    // 0..3: lane within group

    const int pair = warp_id * 8 + group;
    if (pair >= n) return;

    const long long c = (long long)__ldcs(&ctx_idx[pair]);
    const long long t = (long long)__ldcs(&tgt_idx[pair]);

    const float* cv = cxt_w + c * 128 + j * 8;   // lane's 32B slot
    const float* tv = tgt_w + t * 128 + j * 8;

    // 8 independent 32B loads per lane (4 per table) -> 256B in flight/lane
    float a0[8], a1[8], a2[8], a3[8];
    float b0[8], b1[8], b2[8], b3[8];
    ldg256_keep(cv,      a0);
    ldg256_keep(cv + 32, a1);
    ldg256_keep(cv + 64, a2);
    ldg256_keep(cv + 96, a3);
    ldg256_keep(tv,      b0);
    ldg256_keep(tv + 32, b1);
    ldg256_keep(tv + 64, b2);
    ldg256_keep(tv + 96, b3);

    float s0 = 0.f, s1 = 0.f, s2 = 0.f, s3 = 0.f;
    #pragma unroll
    for (int k = 0; k < 8; k++) s0 = fmaf(a0[k], b0[k], s0);
    #pragma unroll
    for (int k = 0; k < 8; k++) s1 = fmaf(a1[k], b1[k], s1);
    #pragma unroll
    for (int k = 0; k < 8; k++) s2 = fmaf(a2[k], b2[k], s2);
    #pragma unroll
    for (int k = 0; k < 8; k++) s3 = fmaf(a3[k], b3[k], s3);

    float s = (s0 + s1) + (s2 + s3);

    // butterfly reduce across the 4-lane group (xor 2,1 stays in-group)
    s += __shfl_xor_sync(0xFFFFFFFFu, s, 2);
    s += __shfl_xor_sync(0xFFFFFFFFu, s, 1);

    if (j == 0)
        __stcs(&out[pair], s);
}

extern "C" void kernel_launch(void* const* d_in, const int* in_sizes, int n_in,
                              void* d_out, int out_size)
{
    const int*   ctx_idx = (const int*)d_in[0];
    const int*   tgt_idx = (const int*)d_in[1];
    const float* cxt_w   = (const float*)d_in[2];
    const float* tgt_w   = (const float*)d_in[3];
    float*       out     = (float*)d_out;

    const int n = in_sizes[0];               // 1,000,000 pairs
    const int threads = 128;                 // 4 warps/block, 32 pairs/block
    const int pairs_per_block = (threads / 32) * 8;
    const int blocks = (n + pairs_per_block - 1) / pairs_per_block;

    skipgram_dot_kernel<<<blocks, threads>>>(ctx_idx, tgt_idx, cxt_w, tgt_w, out, n);
}